// round 8
// baseline (speedup 1.0000x reference)
#include <cuda_runtime.h>
#include <cstdint>

// celerite GP factor + solve + loglike. N=262144, J=16, R=4.
// Chunked-parallel scans with OV warm-up (contracting recurrences), ILP-2:
// each warp runs TWO independent chunks phase-interleaved for latency hiding.

#define JDIM 16
#define RDIM 4
#define OV   12
#define NMAX 262144
#define MAXC 8192

__device__ float g_W[(size_t)NMAX * JDIM];     // 16 MB scratch: W rows
__device__ float g_z[(size_t)NMAX * RDIM];     // 4 MB scratch: z rows (/d)
__device__ float g_logd[MAXC];                 // per-chunk sum(log d)
__device__ float g_yx[MAXC * RDIM];            // per-chunk sum(y*x) per RHS

__device__ __forceinline__ float fast_rcp(float x) {
    float r;
    asm("rcp.approx.f32 %0, %1;" : "=f"(r) : "f"(x));
    r = r * (2.0f - x * r);
    return r;
}

// ---------------------------------------------------------------------------
// Kernel 1: fused factorization + forward solve, 2 chunks per warp.
// Lane layout per chain: i = lane&15 (row), h = lane>>4; lane holds
// S[i][8h..8h+8) and F[i][2h..2h+2).
// ---------------------------------------------------------------------------
__global__ void __launch_bounds__(256, 2)
factor_forward_kernel(const float* __restrict__ a, const float* __restrict__ U,
                      const float* __restrict__ V, const float* __restrict__ P,
                      const float* __restrict__ y, int N, int Cw, int L)
{
    int w = (blockIdx.x * blockDim.x + threadIdx.x) >> 5;
    if (w >= Cw) return;
    int lane = threadIdx.x & 31;
    int i = lane & 15;
    int h = lane >> 4;
    const unsigned FULL = 0xffffffffu;

    int chunk[2] = {w, w + Cw};
    int sA[2], lenA[2], row[2];
    bool act[2];
    float s8[2][8], f0[2], f1[2], zp0[2], zp1[2], wprev[2], llogd[2];

#pragma unroll
    for (int c = 0; c < 2; c++) {
        int s = chunk[c] * L;
        act[c] = (s < N);
        if (!act[c]) s = 0;
        int e = min(s + L, N);
        int m0 = max(0, s - OV);
        sA[c] = s;
        lenA[c] = act[c] ? (e - m0 - 1) : 0;
        row[c] = m0 + 1;
        llogd[c] = 0.f;

        // init state at row m0
        float an = a[m0];
        float vi = V[(size_t)m0 * JDIM + i];
        float dn = an;
        float rd = fast_rcp(dn);
        float wi = vi * rd;
        float wj[8];
#pragma unroll
        for (int k = 0; k < 8; k++) wj[k] = __shfl_sync(FULL, wi, 8 * h + k);
        float dw = dn * wi;
#pragma unroll
        for (int k = 0; k < 8; k++) s8[c][k] = dw * wj[k];
        float2 y2 = *(const float2*)(y + (size_t)m0 * RDIM + 2 * h);
        zp0[c] = y2.x; zp1[c] = y2.y;
        f0[c] = 0.f; f1[c] = 0.f;
        wprev[c] = wi;

        if (act[c] && m0 == s) {   // chunk 0 only: store row 0
            if (h == 0) g_W[(size_t)m0 * JDIM + i] = wi;
            if (i == 0) *(float2*)(g_z + (size_t)m0 * RDIM + 2 * h) =
                            make_float2(y2.x * rd, y2.y * rd);
            llogd[c] += __logf(dn);
        }
    }

    int T = max(lenA[0], lenA[1]);

#pragma unroll 1
    for (int t = 0; t < T; t++) {
        // phase 1: loads, both chains
        float pjk[2][8], ujk[2][8], pi2[2], ui2[2], vi2[2], an2[2];
        float2 yy[2];
#pragma unroll
        for (int c = 0; c < 2; c++) {
            size_t rb = (size_t)row[c] * JDIM;
            const float* Pr = P + rb - JDIM;
            const float* Ur = U + rb;
            float4 q0 = *(const float4*)(Pr + 8 * h);
            float4 q1 = *(const float4*)(Pr + 8 * h + 4);
            pjk[c][0]=q0.x; pjk[c][1]=q0.y; pjk[c][2]=q0.z; pjk[c][3]=q0.w;
            pjk[c][4]=q1.x; pjk[c][5]=q1.y; pjk[c][6]=q1.z; pjk[c][7]=q1.w;
            pi2[c] = Pr[i];
            float4 u0 = *(const float4*)(Ur + 8 * h);
            float4 u1 = *(const float4*)(Ur + 8 * h + 4);
            ujk[c][0]=u0.x; ujk[c][1]=u0.y; ujk[c][2]=u0.z; ujk[c][3]=u0.w;
            ujk[c][4]=u1.x; ujk[c][5]=u1.y; ujk[c][6]=u1.z; ujk[c][7]=u1.w;
            ui2[c] = Ur[i];
            vi2[c] = V[rb + i];
            an2[c] = a[row[c]];
            yy[c]  = *(const float2*)(y + (size_t)row[c] * RDIM + 2 * h);
        }

        // phase 2: F recurrence
#pragma unroll
        for (int c = 0; c < 2; c++) {
            f0[c] = pi2[c] * (f0[c] + wprev[c] * zp0[c]);
            f1[c] = pi2[c] * (f1[c] + wprev[c] * zp1[c]);
        }

        // phase 3: S decay + row-dot
        float su[2];
#pragma unroll
        for (int c = 0; c < 2; c++) {
#pragma unroll
            for (int k = 0; k < 8; k++) s8[c][k] *= pi2[c] * pjk[c][k];
            float t01 = fmaf(s8[c][1], ujk[c][1], s8[c][0] * ujk[c][0]);
            float t23 = fmaf(s8[c][3], ujk[c][3], s8[c][2] * ujk[c][2]);
            float t45 = fmaf(s8[c][5], ujk[c][5], s8[c][4] * ujk[c][4]);
            float t67 = fmaf(s8[c][7], ujk[c][7], s8[c][6] * ujk[c][6]);
            su[c] = (t01 + t23) + (t45 + t67);
        }
#pragma unroll
        for (int c = 0; c < 2; c++)
            su[c] += __shfl_xor_sync(FULL, su[c], 16);

        // phase 4: interleaved butterflies (6 values x 4 levels)
        float tD[2], t0v[2], t1v[2];
#pragma unroll
        for (int c = 0; c < 2; c++) {
            tD[c]  = ui2[c] * su[c];
            t0v[c] = ui2[c] * f0[c];
            t1v[c] = ui2[c] * f1[c];
        }
#pragma unroll
        for (int o = 1; o <= 8; o <<= 1) {
#pragma unroll
            for (int c = 0; c < 2; c++) {
                tD[c]  += __shfl_xor_sync(FULL, tD[c],  o);
                t0v[c] += __shfl_xor_sync(FULL, t0v[c], o);
                t1v[c] += __shfl_xor_sync(FULL, t1v[c], o);
            }
        }

        // phase 5: d, w, z, stores, S rank-1 update
#pragma unroll
        for (int c = 0; c < 2; c++) {
            float dn = an2[c] - tD[c];
            float rd = fast_rcp(dn);
            float wi = (vi2[c] - su[c]) * rd;
            float zn0 = yy[c].x - t0v[c];
            float zn1 = yy[c].y - t1v[c];

            bool pr = (t < lenA[c]) && (row[c] >= sA[c]);
            if (pr && h == 0) g_W[(size_t)row[c] * JDIM + i] = wi;
            if (pr && i == 0) *(float2*)(g_z + (size_t)row[c] * RDIM + 2 * h) =
                                  make_float2(zn0 * rd, zn1 * rd);
            llogd[c] += pr ? __logf(dn) : 0.f;

            float wj[8];
#pragma unroll
            for (int k = 0; k < 8; k++) wj[k] = __shfl_sync(FULL, wi, 8 * h + k);
            float dw = dn * wi;
#pragma unroll
            for (int k = 0; k < 8; k++) s8[c][k] = fmaf(dw, wj[k], s8[c][k]);

            wprev[c] = wi; zp0[c] = zn0; zp1[c] = zn1;
            row[c] += (t + 1 < lenA[c]) ? 1 : 0;
        }
    }

#pragma unroll
    for (int c = 0; c < 2; c++)
        if (act[c] && lane == 0) g_logd[chunk[c]] = llogd[c];
}

// ---------------------------------------------------------------------------
// Kernel 2: backward solve, 2 chunks per warp, reverse with warm-up.
// Body executes unconditionally; stores/accumulators gated by uniform pred.
// ---------------------------------------------------------------------------
__global__ void __launch_bounds__(256, 3)
backward_kernel(const float* __restrict__ U, const float* __restrict__ P,
                const float* __restrict__ y, float* __restrict__ xout,
                int N, int Cw, int L)
{
    int w = (blockIdx.x * blockDim.x + threadIdx.x) >> 5;
    if (w >= Cw) return;
    int lane = threadIdx.x & 31;
    int i = lane & 15;
    int h = lane >> 4;
    const unsigned FULL = 0xffffffffu;

    int chunk[2] = {w, w + Cw};
    int sA[2], eA[2], lenA[2], row[2];
    bool act[2];
    float g0[2], g1[2], acc0[2], acc1[2];

#pragma unroll
    for (int c = 0; c < 2; c++) {
        int s = chunk[c] * L;
        act[c] = (s < N);
        if (!act[c]) s = 0;
        int e = min(s + L, N);
        sA[c] = s; eA[c] = e;
        g0[c] = g1[c] = 0.f;
        acc0[c] = acc1[c] = 0.f;

        if (act[c] && e == N) {   // last chunk: x[N-1] = z[N-1]
            float2 z2 = *(const float2*)(g_z + (size_t)(N - 1) * RDIM + 2 * h);
            float2 yv = *(const float2*)(y + (size_t)(N - 1) * RDIM + 2 * h);
            if (i == 0) *(float2*)(xout + (size_t)(N - 1) * RDIM + 2 * h) = z2;
            acc0[c] = yv.x * z2.x;
            acc1[c] = yv.y * z2.y;
        }

        int ns = min(e - 1 + OV, N - 2);
        lenA[c] = act[c] ? max(0, ns - s + 1) : 0;
        row[c] = (lenA[c] > 0) ? ns : 0;
    }

    int T = max(lenA[0], lenA[1]);

#pragma unroll 1
    for (int t = 0; t < T; t++) {
        // loads + G recurrence (both chains)
        float wi2[2], t0v[2], t1v[2];
#pragma unroll
        for (int c = 0; c < 2; c++) {
            size_t rb = (size_t)row[c] * JDIM;
            float pi = P[rb + i];
            float u1 = U[rb + JDIM + i];
            float2 z1 = *(const float2*)(g_z + (size_t)(row[c] + 1) * RDIM + 2 * h);
            g0[c] = pi * (g0[c] + u1 * z1.x);
            g1[c] = pi * (g1[c] + u1 * z1.y);
            wi2[c] = g_W[rb + i];
            t0v[c] = wi2[c] * g0[c];
            t1v[c] = wi2[c] * g1[c];
        }
        // interleaved butterflies
#pragma unroll
        for (int o = 1; o <= 8; o <<= 1) {
#pragma unroll
            for (int c = 0; c < 2; c++) {
                t0v[c] += __shfl_xor_sync(FULL, t0v[c], o);
                t1v[c] += __shfl_xor_sync(FULL, t1v[c], o);
            }
        }
        // x, store, accumulate
#pragma unroll
        for (int c = 0; c < 2; c++) {
            float2 zn = *(const float2*)(g_z + (size_t)row[c] * RDIM + 2 * h);
            float x0 = zn.x - t0v[c];
            float x1 = zn.y - t1v[c];
            bool pr = (t < lenA[c]) && (row[c] < eA[c]);
            if (pr && i == 0)
                *(float2*)(xout + (size_t)row[c] * RDIM + 2 * h) = make_float2(x0, x1);
            float2 yv = *(const float2*)(y + (size_t)row[c] * RDIM + 2 * h);
            acc0[c] += pr ? yv.x * x0 : 0.f;
            acc1[c] += pr ? yv.y * x1 : 0.f;
            row[c] -= (t + 1 < lenA[c]) ? 1 : 0;
        }
    }

#pragma unroll
    for (int c = 0; c < 2; c++)
        if (act[c] && i == 0) {
            g_yx[chunk[c] * RDIM + 2 * h + 0] = acc0[c];
            g_yx[chunk[c] * RDIM + 2 * h + 1] = acc1[c];
        }
}

// ---------------------------------------------------------------------------
// Kernel 3: finalize loglike. 4 warps, warp r owns RHS r; lanes stride over
// chunks, fp64 butterfly. Fixed order -> deterministic.
// ---------------------------------------------------------------------------
__global__ void finalize_kernel(float* __restrict__ out, int N, int Cf, int Cb)
{
    const unsigned FULL = 0xffffffffu;
    int wq = threadIdx.x >> 5;
    int lane = threadIdx.x & 31;

    double sl = 0.0;
    for (int c = lane; c < Cf; c += 32) sl += (double)g_logd[c];
#pragma unroll
    for (int o = 16; o > 0; o >>= 1) sl += __shfl_xor_sync(FULL, sl, o);
    double norm = -0.5 * (sl + (double)N * log(6.283185307179586));

    double syx = 0.0;
    for (int c = lane; c < Cb; c += 32) syx += (double)g_yx[c * RDIM + wq];
#pragma unroll
    for (int o = 16; o > 0; o >>= 1) syx += __shfl_xor_sync(FULL, syx, o);

    if (lane == 0 && wq < RDIM)
        out[(size_t)N * RDIM + wq] = (float)(norm - 0.5 * syx);
}

// ---------------------------------------------------------------------------
extern "C" void kernel_launch(void* const* d_in, const int* in_sizes, int n_in,
                              void* d_out, int out_size)
{
    const float* a = (const float*)d_in[0];
    const float* U = (const float*)d_in[1];
    const float* V = (const float*)d_in[2];
    const float* P = (const float*)d_in[3];
    const float* y = (const float*)d_in[4];
    float* out = (float*)d_out;

    int N = in_sizes[0];

    // forward: 148 SMs x 16 warps, 2 chunks/warp = 4736 chunks
    int wf = 2368;
    int Cfp = 2 * wf;
    if (Cfp > MAXC) Cfp = MAXC;
    int Lf = (N + Cfp - 1) / Cfp; if (Lf < 1) Lf = 1;
    int Cf_act = (N + Lf - 1) / Lf;

    // backward: 148 SMs x 24 warps, 2 chunks/warp = 7104 chunks
    int wb = 3552;
    int Cbp = 2 * wb;
    if (Cbp > MAXC) Cbp = MAXC;
    int Lb = (N + Cbp - 1) / Cbp; if (Lb < 1) Lb = 1;
    int Cb_act = (N + Lb - 1) / Lb;

    factor_forward_kernel<<<(wf * 32) / 256, 256>>>(a, U, V, P, y, N, wf, Lf);
    backward_kernel<<<(wb * 32) / 256, 256>>>(U, P, y, out, N, wb, Lb);
    finalize_kernel<<<1, 128>>>(out, N, Cf_act, Cb_act);
}